// round 14
// baseline (speedup 1.0000x reference)
#include <cuda_runtime.h>
#include <math.h>

// Problem constants
#define NB 32     // batch
#define SS 12     // seq len
#define FF 128    // features
#define KH 8      // heads
#define HH 64     // head dim
#define CC 64     // out channels
#define NN 512    // nodes
#define SEGS 8    // n-segments per c2 (512/8 = 64 rows/segment, 16 KB)

#define FEAT_BLOCKS NB            // 32 feature blocks FIRST (wave-1 placement)
#define WF_BLOCKS (CC * SEGS)     // 512 stream blocks
#define TOTAL_BLOCKS (FEAT_BLOCKS + WF_BLOCKS)   // 544 (< 592 resident @ 4/SM)

// Scratch (no allocations allowed)
__device__ float g_v[NB * CC];      // per-batch feature vector v[b][c]
__device__ unsigned int g_vready;   // features-done counter (zero-init)
__device__ unsigned int g_done;     // stream-done counter (for replay reset)

// Shared union: feature 2944 floats | stream 1024+2048=3072 floats
#define SBUF_FLOATS 3072

__global__ void __launch_bounds__(256, 4) kOne(
    const float* __restrict__ Wf,
    const float* __restrict__ x,
    const float* __restrict__ W_heads,
    const float* __restrict__ W_out,
    const float* __restrict__ bf,
    float* __restrict__ out)
{
    __shared__ __align__(16) float sbuf[SBUF_FLOATS];
    int bid = blockIdx.x;
    int tid = threadIdx.x;

    if (bid < FEAT_BLOCKS) {
        // ================= feature role (fast f-parallel path) =================
        // v[b][c] = sum_j elu( x_last[b] . W_heads[:,:,j] ) * W_out[j][c]
        int b = bid;

        float* xl    = sbuf;                 // 128
        float* hpart = sbuf + 128;           // [4 fparts][512 j]
        float* hp    = sbuf + 128 + 2048;    // 512
        float* red   = sbuf + 128 + 2048 + 512; // 256

        // init this batch's out row with bias (base for stream atomics)
        if (tid < CC) out[b * CC + tid] = bf[tid];

        if (tid < 32)
            ((float4*)xl)[tid] = ((const float4*)(x + b * SS * FF + (SS - 1) * FF))[tid];
        __syncthreads();

        // hp partials: 512 slots = 4 f-partitions x 128 j-quads, 2 slots/thread
        #pragma unroll
        for (int s = 0; s < 2; ++s) {
            int slot  = tid + s * 256;       // 0..511
            int fpart = slot >> 7;           // 0..3
            int jq    = slot & 127;          // j-quad
            int k     = jq >> 4;             // head index
            int h0    = (jq & 15) * 4;
            const float4* w = (const float4*)(W_heads + (size_t)k * FF * HH + h0);
            int f0 = fpart * 32;
            float4 acc = make_float4(0.f, 0.f, 0.f, 0.f);
            #pragma unroll 8
            for (int i = 0; i < 32; ++i) {
                float4 wv = w[(f0 + i) * 16];
                float xv = xl[f0 + i];
                acc.x = fmaf(xv, wv.x, acc.x);
                acc.y = fmaf(xv, wv.y, acc.y);
                acc.z = fmaf(xv, wv.z, acc.z);
                acc.w = fmaf(xv, wv.w, acc.w);
            }
            ((float4*)hpart)[fpart * 128 + jq] = acc;
        }
        __syncthreads();

        // reduce f-partitions + elu
        #pragma unroll
        for (int s = 0; s < 2; ++s) {
            int j = tid + s * 256;
            float sum = (hpart[j] + hpart[512 + j]) + (hpart[1024 + j] + hpart[1536 + j]);
            hp[j] = (sum > 0.f) ? sum : expm1f(sum);   // elu (alpha=1)
        }
        __syncthreads();

        // v[c] = sum_j hp[j]*W_out[j][c]
        {
            int c = tid & 63;
            int part = tid >> 6;
            int j0 = part * 128;
            float acc0 = 0.f, acc1 = 0.f;
            #pragma unroll 16
            for (int j = 0; j < 64; ++j) {
                acc0 = fmaf(hp[j0 + j],      W_out[(j0 + j) * CC + c],      acc0);
                acc1 = fmaf(hp[j0 + 64 + j], W_out[(j0 + 64 + j) * CC + c], acc1);
            }
            red[part * 64 + c] = acc0 + acc1;
        }
        __syncthreads();
        #pragma unroll
        for (int s = 2; s >= 1; s >>= 1) {
            int c = tid & 63;
            int part = tid >> 6;
            if (part < s) red[part * 64 + c] += red[(part + s) * 64 + c];
            __syncthreads();
        }
        if (tid < CC) g_v[b * CC + tid] = red[tid];

        // publish: all writes (out row + g_v row) visible, then signal
        __threadfence();
        __syncthreads();
        if (tid == 0) atomicAdd(&g_vready, 1u);
        return;
    }

    // ================= stream role: (c2, seg) slice + distributed finale =====
    int wb   = bid - FEAT_BLOCKS;
    int c2   = wb >> 3;           // 0..63
    int seg  = wb & 7;            // 0..7
    int lane = tid & 15;          // float4 index within 64-float row
    int g    = tid >> 4;          // 0..15 row-groups (4 rows each)

    float4* sred = (float4*)sbuf;               // 256 float4
    float4* sv4  = (float4*)(sbuf + 1024);      // 512 float4

    // ---- Phase A: stream this (c2, seg) slice (no dependency) ----
    const float4* base = (const float4*)(Wf + (size_t)c2 * (NN * CC));
    int n0 = seg * 64 + g * 4;
    float4 v0 = base[(n0 + 0) * 16 + lane];
    float4 v1 = base[(n0 + 1) * 16 + lane];
    float4 v2 = base[(n0 + 2) * 16 + lane];
    float4 v3 = base[(n0 + 3) * 16 + lane];
    float4 acc;
    acc.x = (v0.x + v1.x) + (v2.x + v3.x);
    acc.y = (v0.y + v1.y) + (v2.y + v3.y);
    acc.z = (v0.z + v1.z) + (v2.z + v3.z);
    acc.w = (v0.w + v1.w) + (v2.w + v3.w);
    sred[g * 16 + lane] = acc;
    __syncthreads();

    #pragma unroll
    for (int s = 8; s >= 1; s >>= 1) {
        if (g < s) {
            float4 o = sred[(g + s) * 16 + lane];
            float4 m = sred[g * 16 + lane];
            m.x += o.x; m.y += o.y; m.z += o.z; m.w += o.w;
            sred[g * 16 + lane] = m;
        }
        __syncthreads();
    }
    // part row now in sred[0..15]

    // ---- wait for features (normally already done: stream Phase A >> features)
    if (tid == 0) {
        while (atomicAdd(&g_vready, 0u) < (unsigned)FEAT_BLOCKS) { }
    }
    __syncthreads();
    __threadfence();   // acquire

    // load all v: 512 float4, 2/thread (L2-hot, broadcast across blocks)
    sv4[tid]       = ((const float4*)g_v)[tid];
    sv4[tid + 256] = ((const float4*)g_v)[tid + 256];
    __syncthreads();

    // ---- Phase B: per-batch dot + atomic accumulate into out ----
    // tid -> b = tid/8 (0..31), part = tid%8 (2 float4 of c each)
    {
        int b = tid >> 3;
        int part = tid & 7;
        float4 a0 = sv4[b * 16 + part * 2 + 0];
        float4 a1 = sv4[b * 16 + part * 2 + 1];
        float4 w0 = sred[part * 2 + 0];
        float4 w1 = sred[part * 2 + 1];
        float d = fmaf(a0.x, w0.x, fmaf(a0.y, w0.y, fmaf(a0.z, w0.z, a0.w * w0.w)));
        d = fmaf(a1.x, w1.x, fmaf(a1.y, w1.y, fmaf(a1.z, w1.z, fmaf(a1.w, w1.w, d))));
        d += __shfl_xor_sync(0xffffffffu, d, 1);
        d += __shfl_xor_sync(0xffffffffu, d, 2);
        d += __shfl_xor_sync(0xffffffffu, d, 4);
        if (part == 0)
            atomicAdd(&out[b * CC + c2], d);
    }

    // ---- reset counters for next graph replay ----
    __syncthreads();
    if (tid == 0) {
        unsigned int f = atomicAdd(&g_done, 1u);
        if (f == WF_BLOCKS - 1) {     // last stream block; all others are past
            g_done   = 0u;
            g_vready = 0u;
            __threadfence();
        }
    }
}

// ---------------------------------------------------------------------------
// Inputs (metadata order):
//   0: x        (32,12,128)   f32
//   1: W_heads  (8,128,64)    f32
//   2: a1_heads (8,64)        f32   (unused: softmax over identical rows is uniform)
//   3: a2_heads (8,64)        f32   (unused)
//   4: W_out    (512,64)      f32
//   5: a1_out   (64)          f32   (unused)
//   6: a2_out   (64)          f32   (unused)
//   7: Wf       (64,32768)    f32
//   8: bf       (64)          f32
// Output: (32,64) f32
// ---------------------------------------------------------------------------
extern "C" void kernel_launch(void* const* d_in, const int* in_sizes, int n_in,
                              void* d_out, int out_size)
{
    const float* x       = (const float*)d_in[0];
    const float* W_heads = (const float*)d_in[1];
    const float* W_out   = (const float*)d_in[4];
    const float* Wf      = (const float*)d_in[7];
    const float* bf      = (const float*)d_in[8];
    float* out = (float*)d_out;

    kOne<<<TOTAL_BLOCKS, 256>>>(Wf, x, W_heads, W_out, bf, out);
}